// round 4
// baseline (speedup 1.0000x reference)
#include <cuda_runtime.h>
#include <cuda_bf16.h>
#include <math.h>

#define ND 10000
#define EMAX 1000000
#define NB_EMB 10000
#define NT_EMB 1000
#define H 64
#define R 8                 // counter replicas per dst
#define NDR (ND * R)        // 80000 counters per edge set

// ---------------- device scratch ---------------------------------------------
__device__ int   g_cnt_b[NDR];
__device__ int   g_cnt_t[NDR];
__device__ int   g_off_b[NDR];
__device__ int   g_off_t[NDR];
__device__ int   g_cur_b[NDR];
__device__ int   g_cur_t[NDR];
__device__ int   g_sorted_b[EMAX];
__device__ int   g_sorted_t[EMAX];
__device__ __nv_bfloat16 g_Rb[NB_EMB * H];
__device__ __nv_bfloat16 g_Rt[NT_EMB * H];
__device__ float g_B[ND * H];
__device__ float g_T[ND * H];
__device__ float g_score[ND];

// ---------------- 1) prep: zero counters + relu+bf16 convert emb tables ------
__global__ void prep_kernel(const float* __restrict__ be,
                            const float* __restrict__ te) {
    int tid = blockIdx.x * blockDim.x + threadIdx.x;
    int stride = gridDim.x * blockDim.x;
    for (int i = tid; i < 2 * NDR; i += stride) {
        if (i < NDR) g_cnt_b[i] = 0;
        else         g_cnt_t[i - NDR] = 0;
    }
    for (int i = tid; i < NB_EMB * H; i += stride)
        g_Rb[i] = __float2bfloat16(fmaxf(be[i], 0.f));
    for (int i = tid; i < NT_EMB * H; i += stride)
        g_Rt[i] = __float2bfloat16(fmaxf(te[i], 0.f));
}

// ---------------- 2) histogram; replica = f(edge index) ----------------------
__global__ void hist_kernel(const int* __restrict__ dstb,
                            const int* __restrict__ dstt, int n) {
    int n4 = n >> 2;
    int total = 2 * n4;
    int g = blockIdx.x * blockDim.x + threadIdx.x;
    int stride = gridDim.x * blockDim.x;
    for (int i = g; i < total; i += stride) {
        int which = (i >= n4);
        int gg = which ? i - n4 : i;
        const int4* d4 = (const int4*)(which ? dstt : dstb);
        int* cnt = which ? g_cnt_t : g_cnt_b;
        int4 d = d4[gg];
        int base = gg << 2;                    // global edge index of d.x
        atomicAdd(&cnt[d.x * R + ((base + 0) & (R - 1))], 1);
        atomicAdd(&cnt[d.y * R + ((base + 1) & (R - 1))], 1);
        atomicAdd(&cnt[d.z * R + ((base + 2) & (R - 1))], 1);
        atomicAdd(&cnt[d.w * R + ((base + 3) & (R - 1))], 1);
    }
    int rem = n & 3;
    if (g < rem) {
        int i = n - 1 - g;
        atomicAdd(&g_cnt_b[dstb[i] * R + (i & (R - 1))], 1);
        atomicAdd(&g_cnt_t[dstt[i] * R + (i & (R - 1))], 1);
    }
}

// ---------------- 3) exclusive scan over NDR counters, two-phase -------------
__global__ void scan_kernel() {
    const int PER = (NDR + 1023) / 1024;   // 79
    __shared__ int wsum[32];
    int lane = threadIdx.x & 31;
    int wid = threadIdx.x >> 5;
    for (int which = 0; which < 2; which++) {
        const int* cnt = which ? g_cnt_t : g_cnt_b;
        int* off = which ? g_off_t : g_off_b;
        int* cur = which ? g_cur_t : g_cur_b;
        int base = threadIdx.x * PER;
        int sum = 0;
        for (int k = 0; k < PER; k++) {
            int idx = base + k;
            if (idx < NDR) sum += cnt[idx];
        }
        int inc = sum;
        #pragma unroll
        for (int o = 1; o < 32; o <<= 1) {
            int t = __shfl_up_sync(0xffffffffu, inc, o);
            if (lane >= o) inc += t;
        }
        if (lane == 31) wsum[wid] = inc;
        __syncthreads();
        if (wid == 0) {
            int w = wsum[lane];
            #pragma unroll
            for (int o = 1; o < 32; o <<= 1) {
                int t = __shfl_up_sync(0xffffffffu, w, o);
                if (lane >= o) w += t;
            }
            wsum[lane] = w;
        }
        __syncthreads();
        int run = inc - sum + (wid > 0 ? wsum[wid - 1] : 0);
        for (int k = 0; k < PER; k++) {
            int idx = base + k;
            if (idx < NDR) {
                int v = cnt[idx];
                off[idx] = run;
                cur[idx] = run;
                run += v;
            }
        }
        __syncthreads();
    }
}

// ---------------- 4) scatter; replica = f(edge index), 8 edges/thread --------
__global__ void scatter_kernel(const int* __restrict__ srcb, const int* __restrict__ dstb,
                               const int* __restrict__ idsb,
                               const int* __restrict__ srct, const int* __restrict__ dstt,
                               const int* __restrict__ idst, int n) {
    int n8 = n >> 3;
    int total = 2 * n8;
    int g = blockIdx.x * blockDim.x + threadIdx.x;
    int stride = gridDim.x * blockDim.x;
    for (int i = g; i < total; i += stride) {
        int which = (i >= n8);
        int gg = which ? i - n8 : i;
        const int4* s4 = (const int4*)(which ? srct : srcb);
        const int4* d4 = (const int4*)(which ? dstt : dstb);
        const int* ids = which ? idst : idsb;
        int* cur = which ? g_cur_t : g_cur_b;
        int* out = which ? g_sorted_t : g_sorted_b;
        int4 da = d4[gg * 2], db = d4[gg * 2 + 1];
        int4 sa = s4[gg * 2], sb = s4[gg * 2 + 1];
        // base edge index = gg*8, divisible by 8 -> reps are exactly 0..7
        int p0 = atomicAdd(&cur[da.x * R + 0], 1);
        int p1 = atomicAdd(&cur[da.y * R + 1], 1);
        int p2 = atomicAdd(&cur[da.z * R + 2], 1);
        int p3 = atomicAdd(&cur[da.w * R + 3], 1);
        int p4 = atomicAdd(&cur[db.x * R + 4], 1);
        int p5 = atomicAdd(&cur[db.y * R + 5], 1);
        int p6 = atomicAdd(&cur[db.z * R + 6], 1);
        int p7 = atomicAdd(&cur[db.w * R + 7], 1);
        int v0 = __ldg(&ids[sa.x]);
        int v1 = __ldg(&ids[sa.y]);
        int v2 = __ldg(&ids[sa.z]);
        int v3 = __ldg(&ids[sa.w]);
        int v4 = __ldg(&ids[sb.x]);
        int v5 = __ldg(&ids[sb.y]);
        int v6 = __ldg(&ids[sb.z]);
        int v7 = __ldg(&ids[sb.w]);
        out[p0] = v0; out[p1] = v1; out[p2] = v2; out[p3] = v3;
        out[p4] = v4; out[p5] = v5; out[p6] = v6; out[p7] = v7;
    }
    int rem = n & 7;
    if (g < rem) {
        int i = n - 1 - g;
        int rep = i & (R - 1);
        int pb = atomicAdd(&g_cur_b[dstb[i] * R + rep], 1);
        g_sorted_b[pb] = idsb[srcb[i]];
        int pt = atomicAdd(&g_cur_t[dstt[i] * R + rep], 1);
        g_sorted_t[pt] = idst[srct[i]];
    }
}

// ---------------- 5) segment aggregation: one warp per dst node --------------
__global__ void agg_kernel(int E) {
    int gw = (blockIdx.x * blockDim.x + threadIdx.x) >> 5;
    int lane = threadIdx.x & 31;
    if (gw >= 2 * ND) return;
    int which = (gw >= ND);
    int d = which ? (gw - ND) : gw;
    const int* off = which ? g_off_t : g_off_b;
    const int* srt = which ? g_sorted_t : g_sorted_b;
    const __nv_bfloat16* emb = which ? g_Rt : g_Rb;
    float* out = which ? g_T : g_B;

    int s = off[d * R];
    int e = (d < ND - 1) ? off[(d + 1) * R] : E;
    int n = e - s;
    float ax = 0.f, ay = 0.f;
    int i = 0;
    for (; i + 8 <= n; i += 8) {
        int id[8];
        #pragma unroll
        for (int k = 0; k < 8; k++) id[k] = __ldg(&srt[s + i + k]);
        __nv_bfloat162 v[8];
        #pragma unroll
        for (int k = 0; k < 8; k++)
            v[k] = __ldg((const __nv_bfloat162*)(emb + (size_t)id[k] * H) + lane);
        #pragma unroll
        for (int k = 0; k < 8; k++) {
            float2 f = __bfloat1622float2(v[k]);
            ax += f.x; ay += f.y;
        }
    }
    for (; i < n; i++) {
        int id = __ldg(&srt[s + i]);
        float2 f = __bfloat1622float2(
            __ldg((const __nv_bfloat162*)(emb + (size_t)id * H) + lane));
        ax += f.x; ay += f.y;
    }
    float2 r; r.x = ax; r.y = ay;
    ((float2*)(out + (size_t)d * H))[lane] = r;
}

// ---------------- 6) fused per-node head -------------------------------------
__global__ void head_kernel(const float* __restrict__ Wb, const float* __restrict__ bb,
                            const float* __restrict__ Wt, const float* __restrict__ bt,
                            const float* __restrict__ Wu, const float* __restrict__ bu,
                            const float* __restrict__ oW1, const float* __restrict__ ob1,
                            const float* __restrict__ oW2, const float* __restrict__ ob2,
                            int E) {
    __shared__ float sWb[64 * 64];
    __shared__ float sWt[64 * 64];
    __shared__ float sbb[64], sbt[64], sbu[64];
    __shared__ float sB[4][64], sT[4][64], sC[4][64], sD[4][64];

    int tid = threadIdx.x;
    for (int k = tid; k < 4096; k += 256) { sWb[k] = Wb[k]; sWt[k] = Wt[k]; }
    if (tid < 64) { sbb[tid] = bb[tid]; sbt[tid] = bt[tid]; sbu[tid] = bu[tid]; }
    __syncthreads();

    int grp = tid >> 6;
    int j   = tid & 63;

    for (int row = blockIdx.x * 4 + grp; row < ND; row += gridDim.x * 4) {
        sB[grp][j] = g_B[(size_t)row * 64 + j];
        sT[grp][j] = g_T[(size_t)row * 64 + j];
        int sb0 = g_off_b[row * R];
        int sb1 = (row < ND - 1) ? g_off_b[(row + 1) * R] : E;
        int st0 = g_off_t[row * R];
        int st1 = (row < ND - 1) ? g_off_t[(row + 1) * R] : E;
        float degb = (float)(sb1 - sb0);
        float degt = (float)(st1 - st0);
        __syncthreads();

        float c = 0.f;
        #pragma unroll 16
        for (int k = 0; k < 64; k++) {
            c += sB[grp][k] * sWb[k * 64 + j];
            c += sT[grp][k] * sWt[k * 64 + j];
        }
        c = 0.5f * (c + degb * sbb[j] + degt * sbt[j]);
        sC[grp][j] = c;
        __syncthreads();

        float dd = sbu[j];
        #pragma unroll 16
        for (int k = 0; k < 64; k++)
            dd += sC[grp][k] * __ldg(&Wu[k * 64 + j]);
        sD[grp][j] = fmaxf(dd, 0.f);
        __syncthreads();

        if (j < 32) {
            float h = __ldg(&ob1[j]);
            #pragma unroll 16
            for (int k = 0; k < 64; k++)
                h += sD[grp][k] * __ldg(&oW1[k * 32 + j]);
            h = fmaxf(h, 0.f);
            float p = h * __ldg(&oW2[j]);
            #pragma unroll
            for (int o = 16; o > 0; o >>= 1)
                p += __shfl_down_sync(0xffffffffu, p, o);
            if (j == 0)
                g_score[row] = 1.f / (1.f + expf(-(p + __ldg(ob2))));
        }
        __syncthreads();
    }
}

// ---------------- 7) output gather, float4 writes ----------------------------
__global__ void out_gather_kernel(const int* __restrict__ inst2type,
                                  float* __restrict__ out, int n) {
    int n4 = n >> 2;
    int i = blockIdx.x * blockDim.x + threadIdx.x;
    int stride = gridDim.x * blockDim.x;
    for (int g = i; g < n4; g += stride) {
        int4 t = ((const int4*)inst2type)[g];
        float4 r;
        r.x = g_score[t.x];
        r.y = g_score[t.y];
        r.z = g_score[t.z];
        r.w = g_score[t.w];
        ((float4*)out)[g] = r;
    }
    int rem = n & 3;
    if (i < rem)
        out[n - 1 - i] = g_score[inst2type[n - 1 - i]];
}

// ---------------- launch ------------------------------------------------------
extern "C" void kernel_launch(void* const* d_in, const int* in_sizes, int n_in,
                              void* d_out, int out_size) {
    const int*   bene_ids      = (const int*)d_in[0];
    const int*   treatment_ids = (const int*)d_in[2];
    const int*   b2d_src       = (const int*)d_in[3];
    const int*   b2d_dst       = (const int*)d_in[4];
    const int*   t2d_src       = (const int*)d_in[5];
    const int*   t2d_dst       = (const int*)d_in[6];
    const int*   inst2type     = (const int*)d_in[7];
    const float* bene_emb      = (const float*)d_in[8];
    const float* treat_emb     = (const float*)d_in[10];
    const float* Wb1 = (const float*)d_in[17];
    const float* bb1 = (const float*)d_in[18];
    const float* Wt1 = (const float*)d_in[19];
    const float* bt1 = (const float*)d_in[20];
    const float* Wu1 = (const float*)d_in[21];
    const float* bu1 = (const float*)d_in[22];
    const float* oW1 = (const float*)d_in[23];
    const float* ob1 = (const float*)d_in[24];
    const float* oW2 = (const float*)d_in[25];
    const float* ob2 = (const float*)d_in[26];

    int E     = in_sizes[3];
    int NINST = in_sizes[7];

    prep_kernel<<<160, 256>>>(bene_emb, treat_emb);
    {
        int blocks = (2 * (E >> 2) + 255) / 256;
        if (blocks > 2048) blocks = 2048;
        if (blocks < 1) blocks = 1;
        hist_kernel<<<blocks, 256>>>(b2d_dst, t2d_dst, E);
    }
    scan_kernel<<<1, 1024>>>();
    {
        int blocks = (2 * (E >> 3) + 255) / 256;
        if (blocks > 2048) blocks = 2048;
        if (blocks < 1) blocks = 1;
        scatter_kernel<<<blocks, 256>>>(b2d_src, b2d_dst, bene_ids,
                                        t2d_src, t2d_dst, treatment_ids, E);
    }
    {
        int warps = 2 * ND;
        int blocks = (warps * 32 + 255) / 256;
        agg_kernel<<<blocks, 256>>>(E);
    }
    head_kernel<<<250, 256>>>(Wb1, bb1, Wt1, bt1, Wu1, bu1, oW1, ob1, oW2, ob2, E);
    {
        int blocks = ((NINST >> 2) + 255) / 256;
        if (blocks < 1) blocks = 1;
        out_gather_kernel<<<blocks, 256>>>(inst2type, (float*)d_out, NINST);
    }
}

// round 5
// speedup vs baseline: 2.2867x; 2.2867x over previous
#include <cuda_runtime.h>
#include <cuda_bf16.h>
#include <math.h>

#define ND 10000
#define EMAX 1000000
#define NB_EMB 10000
#define NT_EMB 1000
#define H 64
#define SCAN_BLK 1024
#define SCAN_NB 10          // 10 blocks * 1024 = 10240 >= ND  (per edge set)

// ---------------- device scratch ---------------------------------------------
__device__ int   g_cnt_b[ND];
__device__ int   g_cnt_t[ND];
__device__ int   g_off_b[ND];
__device__ int   g_off_t[ND];
__device__ int   g_cur_b[ND];
__device__ int   g_cur_t[ND];
__device__ int   g_partials[2 * SCAN_NB];   // per-block sums (b then t)
__device__ int   g_blockoff[2 * SCAN_NB];   // scanned block offsets
__device__ int   g_sorted_b[EMAX];
__device__ int   g_sorted_t[EMAX];
__device__ __nv_bfloat16 g_Rb[NB_EMB * H];
__device__ __nv_bfloat16 g_Rt[NT_EMB * H];
__device__ float g_B[ND * H];
__device__ float g_T[ND * H];
__device__ float g_score[ND];

// ---------------- 1) prep: zero counters + relu+bf16 convert emb tables ------
__global__ void prep_kernel(const float* __restrict__ be,
                            const float* __restrict__ te) {
    int tid = blockIdx.x * blockDim.x + threadIdx.x;
    int stride = gridDim.x * blockDim.x;
    for (int i = tid; i < 2 * ND; i += stride) {
        if (i < ND) g_cnt_b[i] = 0;
        else        g_cnt_t[i - ND] = 0;
    }
    for (int i = tid; i < NB_EMB * H; i += stride)
        g_Rb[i] = __float2bfloat16(fmaxf(be[i], 0.f));
    for (int i = tid; i < NT_EMB * H; i += stride)
        g_Rt[i] = __float2bfloat16(fmaxf(te[i], 0.f));
}

// ---------------- 2) histogram, 8 edges/thread --------------------------------
__global__ void hist_kernel(const int* __restrict__ dstb,
                            const int* __restrict__ dstt, int n) {
    int n8 = n >> 3;
    int total = 2 * n8;
    int g = blockIdx.x * blockDim.x + threadIdx.x;
    int stride = gridDim.x * blockDim.x;
    for (int i = g; i < total; i += stride) {
        int which = (i >= n8);
        int gg = which ? i - n8 : i;
        const int4* d4 = (const int4*)(which ? dstt : dstb);
        int* cnt = which ? g_cnt_t : g_cnt_b;
        int4 da = d4[gg * 2], db = d4[gg * 2 + 1];
        atomicAdd(&cnt[da.x], 1);
        atomicAdd(&cnt[da.y], 1);
        atomicAdd(&cnt[da.z], 1);
        atomicAdd(&cnt[da.w], 1);
        atomicAdd(&cnt[db.x], 1);
        atomicAdd(&cnt[db.y], 1);
        atomicAdd(&cnt[db.z], 1);
        atomicAdd(&cnt[db.w], 1);
    }
    int rem = n & 7;
    if (g < rem) {
        int i = n - 1 - g;
        atomicAdd(&g_cnt_b[dstb[i]], 1);
        atomicAdd(&g_cnt_t[dstt[i]], 1);
    }
}

// ---------------- 3a) per-block partial sums ----------------------------------
__global__ void scan_partials_kernel() {
    __shared__ int sh[32];
    int b = blockIdx.x;                 // 0..2*SCAN_NB-1
    int which = (b >= SCAN_NB);
    int lb = which ? b - SCAN_NB : b;
    const int* cnt = which ? g_cnt_t : g_cnt_b;
    int idx = lb * SCAN_BLK + threadIdx.x;
    int v = (idx < ND) ? cnt[idx] : 0;
    // warp reduce
    #pragma unroll
    for (int o = 16; o > 0; o >>= 1)
        v += __shfl_down_sync(0xffffffffu, v, o);
    int lane = threadIdx.x & 31;
    int wid = threadIdx.x >> 5;
    if (lane == 0) sh[wid] = v;
    __syncthreads();
    if (wid == 0) {
        int w = (lane < SCAN_BLK / 32) ? sh[lane] : 0;
        #pragma unroll
        for (int o = 16; o > 0; o >>= 1)
            w += __shfl_down_sync(0xffffffffu, w, o);
        if (lane == 0) g_partials[b] = w;
    }
}

// ---------------- 3b) scan the 2*SCAN_NB block totals (tiny) ------------------
__global__ void scan_blockoffs_kernel() {
    if (threadIdx.x == 0) {
        int run = 0;
        for (int i = 0; i < SCAN_NB; i++) { g_blockoff[i] = run; run += g_partials[i]; }
        run = 0;
        for (int i = SCAN_NB; i < 2 * SCAN_NB; i++) { g_blockoff[i] = run; run += g_partials[i]; }
    }
}

// ---------------- 3c) per-block exclusive scan + emit -------------------------
__global__ void scan_emit_kernel() {
    __shared__ int wsum[32];
    int b = blockIdx.x;
    int which = (b >= SCAN_NB);
    int lb = which ? b - SCAN_NB : b;
    const int* cnt = which ? g_cnt_t : g_cnt_b;
    int* off = which ? g_off_t : g_off_b;
    int* cur = which ? g_cur_t : g_cur_b;
    int idx = lb * SCAN_BLK + threadIdx.x;
    int v = (idx < ND) ? cnt[idx] : 0;
    int lane = threadIdx.x & 31;
    int wid = threadIdx.x >> 5;
    // warp inclusive scan
    int inc = v;
    #pragma unroll
    for (int o = 1; o < 32; o <<= 1) {
        int t = __shfl_up_sync(0xffffffffu, inc, o);
        if (lane >= o) inc += t;
    }
    if (lane == 31) wsum[wid] = inc;
    __syncthreads();
    if (wid == 0) {
        int w = (lane < SCAN_BLK / 32) ? wsum[lane] : 0;
        #pragma unroll
        for (int o = 1; o < 32; o <<= 1) {
            int t = __shfl_up_sync(0xffffffffu, w, o);
            if (lane >= o) w += t;
        }
        wsum[lane] = w;
    }
    __syncthreads();
    int excl = inc - v + (wid > 0 ? wsum[wid - 1] : 0) + g_blockoff[b];
    if (idx < ND) { off[idx] = excl; cur[idx] = excl; }
}

// ---------------- 4) scatter, 8 edges/thread -----------------------------------
__global__ void scatter_kernel(const int* __restrict__ srcb, const int* __restrict__ dstb,
                               const int* __restrict__ idsb,
                               const int* __restrict__ srct, const int* __restrict__ dstt,
                               const int* __restrict__ idst, int n) {
    int n8 = n >> 3;
    int total = 2 * n8;
    int g = blockIdx.x * blockDim.x + threadIdx.x;
    int stride = gridDim.x * blockDim.x;
    for (int i = g; i < total; i += stride) {
        int which = (i >= n8);
        int gg = which ? i - n8 : i;
        const int4* s4 = (const int4*)(which ? srct : srcb);
        const int4* d4 = (const int4*)(which ? dstt : dstb);
        const int* ids = which ? idst : idsb;
        int* cur = which ? g_cur_t : g_cur_b;
        int* out = which ? g_sorted_t : g_sorted_b;
        int4 da = d4[gg * 2], db = d4[gg * 2 + 1];
        int4 sa = s4[gg * 2], sb = s4[gg * 2 + 1];
        int p0 = atomicAdd(&cur[da.x], 1);
        int p1 = atomicAdd(&cur[da.y], 1);
        int p2 = atomicAdd(&cur[da.z], 1);
        int p3 = atomicAdd(&cur[da.w], 1);
        int p4 = atomicAdd(&cur[db.x], 1);
        int p5 = atomicAdd(&cur[db.y], 1);
        int p6 = atomicAdd(&cur[db.z], 1);
        int p7 = atomicAdd(&cur[db.w], 1);
        int v0 = __ldg(&ids[sa.x]);
        int v1 = __ldg(&ids[sa.y]);
        int v2 = __ldg(&ids[sa.z]);
        int v3 = __ldg(&ids[sa.w]);
        int v4 = __ldg(&ids[sb.x]);
        int v5 = __ldg(&ids[sb.y]);
        int v6 = __ldg(&ids[sb.z]);
        int v7 = __ldg(&ids[sb.w]);
        out[p0] = v0; out[p1] = v1; out[p2] = v2; out[p3] = v3;
        out[p4] = v4; out[p5] = v5; out[p6] = v6; out[p7] = v7;
    }
    int rem = n & 7;
    if (g < rem) {
        int i = n - 1 - g;
        int pb = atomicAdd(&g_cur_b[dstb[i]], 1);
        g_sorted_b[pb] = idsb[srcb[i]];
        int pt = atomicAdd(&g_cur_t[dstt[i]], 1);
        g_sorted_t[pt] = idst[srct[i]];
    }
}

// ---------------- 5) segment aggregation: one warp per dst node ---------------
__global__ void agg_kernel(int E) {
    int gw = (blockIdx.x * blockDim.x + threadIdx.x) >> 5;
    int lane = threadIdx.x & 31;
    if (gw >= 2 * ND) return;
    int which = (gw >= ND);
    int d = which ? (gw - ND) : gw;
    const int* off = which ? g_off_t : g_off_b;
    const int* cnt = which ? g_cnt_t : g_cnt_b;
    const int* srt = which ? g_sorted_t : g_sorted_b;
    const __nv_bfloat16* emb = which ? g_Rt : g_Rb;
    float* out = which ? g_T : g_B;

    int s = off[d];
    int n = cnt[d];
    float ax = 0.f, ay = 0.f;
    int i = 0;
    for (; i + 8 <= n; i += 8) {
        int id[8];
        #pragma unroll
        for (int k = 0; k < 8; k++) id[k] = __ldg(&srt[s + i + k]);
        __nv_bfloat162 v[8];
        #pragma unroll
        for (int k = 0; k < 8; k++)
            v[k] = __ldg((const __nv_bfloat162*)(emb + (size_t)id[k] * H) + lane);
        #pragma unroll
        for (int k = 0; k < 8; k++) {
            float2 f = __bfloat1622float2(v[k]);
            ax += f.x; ay += f.y;
        }
    }
    for (; i < n; i++) {
        int id = __ldg(&srt[s + i]);
        float2 f = __bfloat1622float2(
            __ldg((const __nv_bfloat162*)(emb + (size_t)id * H) + lane));
        ax += f.x; ay += f.y;
    }
    float2 r; r.x = ax; r.y = ay;
    ((float2*)(out + (size_t)d * H))[lane] = r;
}

// ---------------- 6) fused per-node head --------------------------------------
__global__ void head_kernel(const float* __restrict__ Wb, const float* __restrict__ bb,
                            const float* __restrict__ Wt, const float* __restrict__ bt,
                            const float* __restrict__ Wu, const float* __restrict__ bu,
                            const float* __restrict__ oW1, const float* __restrict__ ob1,
                            const float* __restrict__ oW2, const float* __restrict__ ob2) {
    __shared__ float sWb[64 * 64];
    __shared__ float sWt[64 * 64];
    __shared__ float sbb[64], sbt[64], sbu[64];
    __shared__ float sB[4][64], sT[4][64], sC[4][64], sD[4][64];

    int tid = threadIdx.x;
    for (int k = tid; k < 4096; k += 256) { sWb[k] = Wb[k]; sWt[k] = Wt[k]; }
    if (tid < 64) { sbb[tid] = bb[tid]; sbt[tid] = bt[tid]; sbu[tid] = bu[tid]; }
    __syncthreads();

    int grp = tid >> 6;
    int j   = tid & 63;

    for (int row = blockIdx.x * 4 + grp; row < ND; row += gridDim.x * 4) {
        sB[grp][j] = g_B[(size_t)row * 64 + j];
        sT[grp][j] = g_T[(size_t)row * 64 + j];
        float degb = (float)g_cnt_b[row];
        float degt = (float)g_cnt_t[row];
        __syncthreads();

        float c = 0.f;
        #pragma unroll 16
        for (int k = 0; k < 64; k++) {
            c += sB[grp][k] * sWb[k * 64 + j];
            c += sT[grp][k] * sWt[k * 64 + j];
        }
        c = 0.5f * (c + degb * sbb[j] + degt * sbt[j]);
        sC[grp][j] = c;
        __syncthreads();

        float dd = sbu[j];
        #pragma unroll 16
        for (int k = 0; k < 64; k++)
            dd += sC[grp][k] * __ldg(&Wu[k * 64 + j]);
        sD[grp][j] = fmaxf(dd, 0.f);
        __syncthreads();

        if (j < 32) {
            float h = __ldg(&ob1[j]);
            #pragma unroll 16
            for (int k = 0; k < 64; k++)
                h += sD[grp][k] * __ldg(&oW1[k * 32 + j]);
            h = fmaxf(h, 0.f);
            float p = h * __ldg(&oW2[j]);
            #pragma unroll
            for (int o = 16; o > 0; o >>= 1)
                p += __shfl_down_sync(0xffffffffu, p, o);
            if (j == 0)
                g_score[row] = 1.f / (1.f + expf(-(p + __ldg(ob2))));
        }
        __syncthreads();
    }
}

// ---------------- 7) output gather, float4 writes ------------------------------
__global__ void out_gather_kernel(const int* __restrict__ inst2type,
                                  float* __restrict__ out, int n) {
    int n4 = n >> 2;
    int i = blockIdx.x * blockDim.x + threadIdx.x;
    int stride = gridDim.x * blockDim.x;
    for (int g = i; g < n4; g += stride) {
        int4 t = ((const int4*)inst2type)[g];
        float4 r;
        r.x = g_score[t.x];
        r.y = g_score[t.y];
        r.z = g_score[t.z];
        r.w = g_score[t.w];
        ((float4*)out)[g] = r;
    }
    int rem = n & 3;
    if (i < rem)
        out[n - 1 - i] = g_score[inst2type[n - 1 - i]];
}

// ---------------- launch --------------------------------------------------------
extern "C" void kernel_launch(void* const* d_in, const int* in_sizes, int n_in,
                              void* d_out, int out_size) {
    const int*   bene_ids      = (const int*)d_in[0];
    const int*   treatment_ids = (const int*)d_in[2];
    const int*   b2d_src       = (const int*)d_in[3];
    const int*   b2d_dst       = (const int*)d_in[4];
    const int*   t2d_src       = (const int*)d_in[5];
    const int*   t2d_dst       = (const int*)d_in[6];
    const int*   inst2type     = (const int*)d_in[7];
    const float* bene_emb      = (const float*)d_in[8];
    const float* treat_emb     = (const float*)d_in[10];
    const float* Wb1 = (const float*)d_in[17];
    const float* bb1 = (const float*)d_in[18];
    const float* Wt1 = (const float*)d_in[19];
    const float* bt1 = (const float*)d_in[20];
    const float* Wu1 = (const float*)d_in[21];
    const float* bu1 = (const float*)d_in[22];
    const float* oW1 = (const float*)d_in[23];
    const float* ob1 = (const float*)d_in[24];
    const float* oW2 = (const float*)d_in[25];
    const float* ob2 = (const float*)d_in[26];

    int E     = in_sizes[3];
    int NINST = in_sizes[7];

    prep_kernel<<<160, 256>>>(bene_emb, treat_emb);
    {
        int blocks = (2 * (E >> 3) + 255) / 256;
        if (blocks > 2048) blocks = 2048;
        if (blocks < 1) blocks = 1;
        hist_kernel<<<blocks, 256>>>(b2d_dst, t2d_dst, E);
    }
    scan_partials_kernel<<<2 * SCAN_NB, SCAN_BLK>>>();
    scan_blockoffs_kernel<<<1, 32>>>();
    scan_emit_kernel<<<2 * SCAN_NB, SCAN_BLK>>>();
    {
        int blocks = (2 * (E >> 3) + 255) / 256;
        if (blocks > 2048) blocks = 2048;
        if (blocks < 1) blocks = 1;
        scatter_kernel<<<blocks, 256>>>(b2d_src, b2d_dst, bene_ids,
                                        t2d_src, t2d_dst, treatment_ids, E);
    }
    {
        int warps = 2 * ND;
        int blocks = (warps * 32 + 255) / 256;
        agg_kernel<<<blocks, 256>>>(E);
    }
    head_kernel<<<250, 256>>>(Wb1, bb1, Wt1, bt1, Wu1, bu1, oW1, ob1, oW2, ob2);
    {
        int blocks = ((NINST >> 2) + 255) / 256;
        if (blocks < 1) blocks = 1;
        out_gather_kernel<<<blocks, 256>>>(inst2type, (float*)d_out, NINST);
    }
}